// round 10
// baseline (speedup 1.0000x reference)
#include <cuda_runtime.h>
#include <cuda_bf16.h>
#include <cstdint>

// ============================================================================
// GPConv1d: geometric-product conv == dense 1D conv after contracting G into W.
//   x: (8, 64, 8, 4096) f32   W: (5, 64, 64, 8) f32   b: (512) f32   G: (8,8,8) f32
//   out: (8, 64, 8, 4096) f32
//   GEMM-conv: Cout=Cin=512, taps=5, pad=2, L=4096, B=8
//
// Engine: mma.sync bf16 (HMMA) with hi/lo split (3 passes) for fp32-grade
// accuracy. tcgen05 is unusable: harness PTX target is sm_103 (non-'a'), which
// rejects all tcgen05/TMEM instructions.
// ============================================================================
#define NB   8
#define NCH  512
#define NL   4096
#define NLP  4100
#define NTAP 5

#define TM   128          // oc per CTA
#define TN   128          // l per CTA
#define TKC  64           // ic per K-chunk
#define NCHUNK 40         // 5 taps * 8 ic-chunks

// SMEM stage: A(Wh,Wl) 128x64 bf16 + B(Xh,Xl) 128x64 bf16, SW128-swizzled rows
#define OFF_AWH 0
#define OFF_AWL 16384
#define OFF_BXH 32768
#define OFF_BXL 49152
#define STAGE   65536
#define DYN_SMEM (2*STAGE + 1024)

// ============================================================================
// Device scratch (static __device__ arrays — sanctioned no-alloc scratch)
// ============================================================================
__device__ __align__(16) __nv_bfloat16 g_Wh[(size_t)NTAP * NCH * NCH];
__device__ __align__(16) __nv_bfloat16 g_Wl[(size_t)NTAP * NCH * NCH];
__device__ __align__(16) __nv_bfloat16 g_Xh[(size_t)NB * NLP * NCH];
__device__ __align__(16) __nv_bfloat16 g_Xl[(size_t)NB * NLP * NCH];

// ============================================================================
// Helpers (all sm_80-baseline PTX; compiles for plain sm_103 target)
// ============================================================================
__device__ __forceinline__ uint32_t smem_u32(const void* p) {
    return (uint32_t)__cvta_generic_to_shared(p);
}

// SW128 swizzle within a 128B-row tile: 16B chunk c of row r -> chunk c^(r&7)
__device__ __forceinline__ uint32_t swz(uint32_t row, uint32_t colb) {
    return row * 128u + (colb ^ ((row & 7u) * 16u));
}

__device__ __forceinline__ void cp16(uint32_t dst, const void* src) {
    asm volatile("cp.async.cg.shared.global [%0], [%1], 16;"
                 :: "r"(dst), "l"(src));
}
#define CP_COMMIT() asm volatile("cp.async.commit_group;" ::: "memory")
#define CP_WAIT1()  asm volatile("cp.async.wait_group 1;" ::: "memory")

__device__ __forceinline__ void ldsm4(uint32_t& r0, uint32_t& r1,
                                      uint32_t& r2, uint32_t& r3, uint32_t a) {
    asm volatile("ldmatrix.sync.aligned.m8n8.x4.shared.b16 {%0,%1,%2,%3}, [%4];"
                 : "=r"(r0), "=r"(r1), "=r"(r2), "=r"(r3) : "r"(a));
}

__device__ __forceinline__ void mma16816(float* d, const uint32_t* a,
                                         const uint32_t* b) {
    asm volatile(
        "mma.sync.aligned.m16n8k16.row.col.f32.bf16.bf16.f32 "
        "{%0,%1,%2,%3}, {%4,%5,%6,%7}, {%8,%9}, {%0,%1,%2,%3};"
        : "+f"(d[0]), "+f"(d[1]), "+f"(d[2]), "+f"(d[3])
        : "r"(a[0]), "r"(a[1]), "r"(a[2]), "r"(a[3]), "r"(b[0]), "r"(b[1]));
}

// ============================================================================
// Precompute 1: kern_v[oc, ic] = G[j^k, j, k] * W[v, c, o, j^k], split bf16 hi/lo
//   oc = o*8 + k, ic = c*8 + j.   Layout: g_W*[v][oc][ic]
// ============================================================================
__global__ void build_kern(const float* __restrict__ W, const float* __restrict__ G) {
    int idx = blockIdx.x * 256 + threadIdx.x;
    if (idx >= NTAP * NCH * NCH) return;
    int ic = idx & 511;
    int oc = (idx >> 9) & 511;
    int v  = idx >> 18;
    int o = oc >> 3, kb = oc & 7;
    int c = ic >> 3, j  = ic & 7;
    int i = j ^ kb;
    float sign = G[(i * 8 + j) * 8 + kb];
    float val  = sign * W[(((v * 64) + c) * 64 + o) * 8 + i];
    __nv_bfloat16 hi = __float2bfloat16(val);
    float lof = val - __bfloat162float(hi);
    g_Wh[idx] = hi;
    g_Wl[idx] = __float2bfloat16(lof);
}

// ============================================================================
// Precompute 2: padded transpose of x -> g_X*[b][lp][ic] bf16 hi/lo
//   x layout: [b][c][j][l], ic = c*8 + j, lp = l + 2 (pad 2 each side)
// ============================================================================
__global__ void build_x(const float* __restrict__ x) {
    __shared__ float s[32][65];
    const int tid = threadIdx.x;
    const int b   = blockIdx.z;
    const int ic0 = blockIdx.y * 32;
    const int lp0 = blockIdx.x * 64;

    for (int e = tid; e < 2048; e += 256) {
        int icl = e >> 6, lpl = e & 63;
        int lp = lp0 + lpl;
        int l  = lp - 2;
        int ic = ic0 + icl;
        int c = ic >> 3, j = ic & 7;
        float v = 0.f;
        if (l >= 0 && l < NL && lp < NLP)
            v = x[(((size_t)(b * 64 + c)) * 8 + j) * NL + l];
        s[icl][lpl] = v;
    }
    __syncthreads();
    for (int e = tid; e < 2048; e += 256) {
        int lpl = e >> 5, icl = e & 31;
        int lp = lp0 + lpl;
        if (lp < NLP) {
            float val = s[icl][lpl];
            __nv_bfloat16 hi = __float2bfloat16(val);
            float lof = val - __bfloat162float(hi);
            size_t oidx = ((size_t)b * NLP + lp) * NCH + ic0 + icl;
            g_Xh[oidx] = hi;
            g_Xl[oidx] = __float2bfloat16(lof);
        }
    }
}

// ============================================================================
// Main kernel: pipelined split-bf16 HMMA GEMM conv.
//   Per CTA: D[128 oc, 128 l] fp32 in registers; 40 K-chunks of 64.
//   grid = (32 l-tiles, 4 oc-tiles, 8 batch), 256 threads (8 warps, 4x2).
// ============================================================================
__global__ __launch_bounds__(256, 1)
void gpconv_main(const float* __restrict__ bias, float* __restrict__ out) {
    extern __shared__ char dsm_raw[];
    const int tid  = threadIdx.x;
    const int wid  = tid >> 5;
    const int lane = tid & 31;
    const int l0   = blockIdx.x * TN;
    const int oc0  = blockIdx.y * TM;
    const int bb   = blockIdx.z;

    const uint32_t raw   = smem_u32(dsm_raw);
    const uint32_t sbase = (raw + 1023u) & ~1023u;

    const int warp_m0 = (wid & 3) * 32;   // 4 warps over M=128
    const int warp_n0 = (wid >> 2) * 64;  // 2 warps over N=128

    float acc[2][8][4];
    #pragma unroll
    for (int mt = 0; mt < 2; ++mt)
        #pragma unroll
        for (int nt = 0; nt < 8; ++nt)
            #pragma unroll
            for (int q = 0; q < 4; ++q) acc[mt][nt][q] = 0.f;

    // ---- stage loader: chunk c -> buffer (c&1) ----
    auto issue = [&](int c) {
        const int v_tap = c >> 3;
        const int ic0   = (c & 7) << 6;
        const uint32_t so = sbase + (uint32_t)(c & 1) * STAGE;
        // A: kern tile [128 oc x 64 ic] hi+lo
        const size_t gb = (((size_t)v_tap * NCH) + oc0) * NCH + ic0;
        #pragma unroll
        for (int e = tid; e < 1024; e += 256) {
            int row = e >> 3, seg = e & 7;
            size_t gi = gb + (size_t)row * NCH + seg * 8;
            uint32_t off = swz((uint32_t)row, (uint32_t)seg * 16u);
            cp16(so + OFF_AWH + off, g_Wh + gi);
            cp16(so + OFF_AWL + off, g_Wl + gi);
        }
        // B: x tile [128 pos x 64 ic] hi+lo
        const size_t xb = (((size_t)bb * NLP) + (size_t)(l0 + v_tap)) * NCH + ic0;
        #pragma unroll
        for (int e = tid; e < 1024; e += 256) {
            int row = e >> 3, seg = e & 7;
            size_t gi = xb + (size_t)row * NCH + seg * 8;
            uint32_t off = swz((uint32_t)row, (uint32_t)seg * 16u);
            cp16(so + OFF_BXH + off, g_Xh + gi);
            cp16(so + OFF_BXL + off, g_Xl + gi);
        }
    };

    issue(0); CP_COMMIT();
    issue(1); CP_COMMIT();

    // per-lane ldmatrix address components
    const uint32_t a_row  = lane & 15;
    const uint32_t a_col  = (uint32_t)(lane >> 4) * 16u;
    const uint32_t b_row  = (uint32_t)((lane & 7) | ((lane & 16) >> 1));
    const uint32_t b_col  = (uint32_t)((lane >> 3) & 1) * 16u;

    for (int c = 0; c < NCHUNK; ++c) {
        CP_WAIT1();
        __syncthreads();
        const uint32_t so = sbase + (uint32_t)(c & 1) * STAGE;

        #pragma unroll
        for (int s = 0; s < 4; ++s) {
            uint32_t aWh[2][4], aWl[2][4], bXh[8][2], bXl[8][2];
            #pragma unroll
            for (int mt = 0; mt < 2; ++mt) {
                uint32_t off = swz((uint32_t)(warp_m0 + mt * 16) + a_row,
                                   (uint32_t)s * 32u + a_col);
                ldsm4(aWh[mt][0], aWh[mt][1], aWh[mt][2], aWh[mt][3],
                      so + OFF_AWH + off);
                ldsm4(aWl[mt][0], aWl[mt][1], aWl[mt][2], aWl[mt][3],
                      so + OFF_AWL + off);
            }
            #pragma unroll
            for (int np = 0; np < 4; ++np) {    // each x4 covers 2 n8-tiles
                uint32_t off = swz((uint32_t)(warp_n0 + np * 16) + b_row,
                                   (uint32_t)s * 32u + b_col);
                ldsm4(bXh[2 * np][0], bXh[2 * np][1],
                      bXh[2 * np + 1][0], bXh[2 * np + 1][1],
                      so + OFF_BXH + off);
                ldsm4(bXl[2 * np][0], bXl[2 * np][1],
                      bXl[2 * np + 1][0], bXl[2 * np + 1][1],
                      so + OFF_BXL + off);
            }
            #pragma unroll
            for (int mt = 0; mt < 2; ++mt)
                #pragma unroll
                for (int nt = 0; nt < 8; ++nt) {
                    mma16816(acc[mt][nt], aWh[mt], bXh[nt]);   // Wh*Xh
                    mma16816(acc[mt][nt], aWh[mt], bXl[nt]);   // Wh*Xl
                    mma16816(acc[mt][nt], aWl[mt], bXh[nt]);   // Wl*Xh
                }
        }

        __syncthreads();
        if (c + 2 < NCHUNK) issue(c + 2);
        CP_COMMIT();   // always commit (possibly empty) to keep group counts aligned
    }

    // ---- Epilogue: registers -> gmem, + bias ----
    const int r0 = lane >> 2;
    const int cq = (lane & 3) * 2;
    #pragma unroll
    for (int mt = 0; mt < 2; ++mt) {
        const int row0 = oc0 + warp_m0 + mt * 16 + r0;
        const float bv0 = bias[row0];
        const float bv1 = bias[row0 + 8];
        float* p0 = out + ((size_t)(bb * NCH + row0)) * NL + l0 + warp_n0 + cq;
        float* p1 = p0 + (size_t)8 * NL;
        #pragma unroll
        for (int nt = 0; nt < 8; ++nt) {
            float2 v0 = { acc[mt][nt][0] + bv0, acc[mt][nt][1] + bv0 };
            float2 v1 = { acc[mt][nt][2] + bv1, acc[mt][nt][3] + bv1 };
            *(float2*)(p0 + nt * 8) = v0;
            *(float2*)(p1 + nt * 8) = v1;
        }
    }
}

// ============================================================================
// kernel_launch
//   d_in[0]=x   d_in[1]=W   d_in[2]=b (512)   d_in[3]=G   d_out f32
// ============================================================================
extern "C" void kernel_launch(void* const* d_in, const int* in_sizes, int n_in,
                              void* d_out, int out_size) {
    const float* x = (const float*)d_in[0];
    const float* W = (const float*)d_in[1];
    const float* b = (const float*)d_in[2];
    const float* G = (const float*)d_in[3];
    float* out = (float*)d_out;

    build_kern<<<(NTAP * NCH * NCH) / 256, 256>>>(W, G);
    build_x<<<dim3((NLP + 63) / 64, NCH / 32, NB), 256>>>(x);

    cudaFuncSetAttribute(gpconv_main,
                         cudaFuncAttributeMaxDynamicSharedMemorySize, DYN_SMEM);
    gpconv_main<<<dim3(NL / TN, NCH / TM, NB), 256, DYN_SMEM>>>(b, out);
}

// round 11
// speedup vs baseline: 2.0328x; 2.0328x over previous
#include <cuda_runtime.h>
#include <cuda_fp16.h>
#include <cstdint>

// ============================================================================
// GPConv1d: geometric-product conv == dense 1D conv after contracting G into W.
//   x: (8, 64, 8, 4096) f32   W: (5, 64, 64, 8) f32   b: (512) f32   G: (8,8,8) f32
//   out: (8, 64, 8, 4096) f32
//   GEMM-conv: Cout=Cin=512, taps=5, pad=2, L=4096, B=8
//
// Engine: single-pass fp16 mma.sync (HMMA) with fp32 accumulate.
//   fp16 operand quantization -> expected norm rel_err ~3.5e-4 (< 1e-3 budget),
//   at 1/3 the MMA work of the previous split-bf16 3-pass kernel.
// tcgen05 remains unusable: harness PTX target is sm_103 (non-'a').
// ============================================================================
#define NB   8
#define NCH  512
#define NL   4096
#define NLP  4100
#define NTAP 5

#define TM   128          // oc per CTA
#define TN   128          // l per CTA
#define NCHUNK 40         // 5 taps * 8 ic-chunks of 64

// SMEM stage: A(W) 128x64 fp16 + B(X) 128x64 fp16, SW128-swizzled rows
#define OFF_A   0
#define OFF_B   16384
#define STAGE   32768
#define NSTAGE  4
#define DYN_SMEM (NSTAGE*STAGE + 1024)

// ============================================================================
// Device scratch (static __device__ arrays — sanctioned no-alloc scratch)
// ============================================================================
__device__ __align__(16) __half g_Wf[(size_t)NTAP * NCH * NCH];
__device__ __align__(16) __half g_Xf[(size_t)NB * NLP * NCH];

// ============================================================================
// Helpers (sm_80-baseline PTX; compiles for plain sm_103 target)
// ============================================================================
__device__ __forceinline__ uint32_t smem_u32(const void* p) {
    return (uint32_t)__cvta_generic_to_shared(p);
}

// SW128 swizzle within a 128B-row tile: 16B chunk c of row r -> chunk c^(r&7)
__device__ __forceinline__ uint32_t swz(uint32_t row, uint32_t colb) {
    return row * 128u + (colb ^ ((row & 7u) * 16u));
}

__device__ __forceinline__ void cp16(uint32_t dst, const void* src) {
    asm volatile("cp.async.cg.shared.global [%0], [%1], 16;"
                 :: "r"(dst), "l"(src));
}
#define CP_COMMIT() asm volatile("cp.async.commit_group;" ::: "memory")
#define CP_WAIT2()  asm volatile("cp.async.wait_group 2;" ::: "memory")

__device__ __forceinline__ void ldsm4(uint32_t& r0, uint32_t& r1,
                                      uint32_t& r2, uint32_t& r3, uint32_t a) {
    asm volatile("ldmatrix.sync.aligned.m8n8.x4.shared.b16 {%0,%1,%2,%3}, [%4];"
                 : "=r"(r0), "=r"(r1), "=r"(r2), "=r"(r3) : "r"(a));
}

__device__ __forceinline__ void mma16816(float* d, const uint32_t* a,
                                         const uint32_t* b) {
    asm volatile(
        "mma.sync.aligned.m16n8k16.row.col.f32.f16.f16.f32 "
        "{%0,%1,%2,%3}, {%4,%5,%6,%7}, {%8,%9}, {%0,%1,%2,%3};"
        : "+f"(d[0]), "+f"(d[1]), "+f"(d[2]), "+f"(d[3])
        : "r"(a[0]), "r"(a[1]), "r"(a[2]), "r"(a[3]), "r"(b[0]), "r"(b[1]));
}

// ============================================================================
// Precompute 1: kern_v[oc, ic] = G[j^k, j, k] * W[v, c, o, j^k]  -> fp16
//   oc = o*8 + k, ic = c*8 + j.   Layout: g_Wf[v][oc][ic]
// ============================================================================
__global__ void build_kern(const float* __restrict__ W, const float* __restrict__ G) {
    int idx = blockIdx.x * 256 + threadIdx.x;
    if (idx >= NTAP * NCH * NCH) return;
    int ic = idx & 511;
    int oc = (idx >> 9) & 511;
    int v  = idx >> 18;
    int o = oc >> 3, kb = oc & 7;
    int c = ic >> 3, j  = ic & 7;
    int i = j ^ kb;
    float sign = G[(i * 8 + j) * 8 + kb];
    float val  = sign * W[(((v * 64) + c) * 64 + o) * 8 + i];
    g_Wf[idx] = __float2half_rn(val);
}

// ============================================================================
// Precompute 2: padded transpose of x -> g_Xf[b][lp][ic]  fp16
//   x layout: [b][c][j][l], ic = c*8 + j, lp = l + 2 (pad 2 each side)
// ============================================================================
__global__ void build_x(const float* __restrict__ x) {
    __shared__ float s[32][65];
    const int tid = threadIdx.x;
    const int b   = blockIdx.z;
    const int ic0 = blockIdx.y * 32;
    const int lp0 = blockIdx.x * 64;

    for (int e = tid; e < 2048; e += 256) {
        int icl = e >> 6, lpl = e & 63;
        int lp = lp0 + lpl;
        int l  = lp - 2;
        int ic = ic0 + icl;
        int c = ic >> 3, j = ic & 7;
        float v = 0.f;
        if (l >= 0 && l < NL && lp < NLP)
            v = x[(((size_t)(b * 64 + c)) * 8 + j) * NL + l];
        s[icl][lpl] = v;
    }
    __syncthreads();
    for (int e = tid; e < 2048; e += 256) {
        int lpl = e >> 5, icl = e & 31;
        int lp = lp0 + lpl;
        if (lp < NLP) {
            size_t oidx = ((size_t)b * NLP + lp) * NCH + ic0 + icl;
            g_Xf[oidx] = __float2half_rn(s[icl][lpl]);
        }
    }
}

// ============================================================================
// Main kernel: 4-stage pipelined fp16 HMMA GEMM conv.
//   Per CTA: D[128 oc, 128 l] fp32 in registers; 40 K-chunks of 64.
//   grid = (32 l-tiles, 4 oc-tiles, 8 batch), 256 threads (8 warps, 4x2).
// ============================================================================
__global__ __launch_bounds__(256, 1)
void gpconv_main(const float* __restrict__ bias, float* __restrict__ out) {
    extern __shared__ char dsm_raw[];
    const int tid  = threadIdx.x;
    const int wid  = tid >> 5;
    const int lane = tid & 31;
    const int l0   = blockIdx.x * TN;
    const int oc0  = blockIdx.y * TM;
    const int bb   = blockIdx.z;

    const uint32_t raw   = smem_u32(dsm_raw);
    const uint32_t sbase = (raw + 1023u) & ~1023u;

    const int warp_m0 = (wid & 3) * 32;   // 4 warps over M=128
    const int warp_n0 = (wid >> 2) * 64;  // 2 warps over N=128

    float acc[2][8][4];
    #pragma unroll
    for (int mt = 0; mt < 2; ++mt)
        #pragma unroll
        for (int nt = 0; nt < 8; ++nt)
            #pragma unroll
            for (int q = 0; q < 4; ++q) acc[mt][nt][q] = 0.f;

    // ---- stage loader: chunk c -> buffer (c % NSTAGE) ----
    auto issue = [&](int c) {
        const int v_tap = c >> 3;
        const int ic0   = (c & 7) << 6;
        const uint32_t so = sbase + (uint32_t)(c & (NSTAGE - 1)) * STAGE;
        // A: kern tile [128 oc x 64 ic]
        const size_t gb = (((size_t)v_tap * NCH) + oc0) * NCH + ic0;
        // B: x tile [128 pos x 64 ic]
        const size_t xb = (((size_t)bb * NLP) + (size_t)(l0 + v_tap)) * NCH + ic0;
        #pragma unroll
        for (int e = tid; e < 1024; e += 256) {
            int row = e >> 3, seg = e & 7;
            uint32_t off = swz((uint32_t)row, (uint32_t)seg * 16u);
            cp16(so + OFF_A + off, g_Wf + gb + (size_t)row * NCH + seg * 8);
            cp16(so + OFF_B + off, g_Xf + xb + (size_t)row * NCH + seg * 8);
        }
    };

    issue(0); CP_COMMIT();
    issue(1); CP_COMMIT();
    issue(2); CP_COMMIT();

    // per-lane ldmatrix address components
    const uint32_t a_row  = lane & 15;
    const uint32_t a_col  = (uint32_t)(lane >> 4) * 16u;
    const uint32_t b_row  = (uint32_t)((lane & 7) | ((lane & 16) >> 1));
    const uint32_t b_col  = (uint32_t)((lane >> 3) & 1) * 16u;

    for (int c = 0; c < NCHUNK; ++c) {
        CP_WAIT2();            // oldest of the <=3 pending groups (stage c) done
        __syncthreads();
        const uint32_t so = sbase + (uint32_t)(c & (NSTAGE - 1)) * STAGE;

        #pragma unroll
        for (int s = 0; s < 4; ++s) {
            uint32_t aW[2][4], bX[8][2];
            #pragma unroll
            for (int mt = 0; mt < 2; ++mt) {
                uint32_t off = swz((uint32_t)(warp_m0 + mt * 16) + a_row,
                                   (uint32_t)s * 32u + a_col);
                ldsm4(aW[mt][0], aW[mt][1], aW[mt][2], aW[mt][3],
                      so + OFF_A + off);
            }
            #pragma unroll
            for (int np = 0; np < 4; ++np) {    // each x4 covers 2 n8-tiles
                uint32_t off = swz((uint32_t)(warp_n0 + np * 16) + b_row,
                                   (uint32_t)s * 32u + b_col);
                ldsm4(bX[2 * np][0], bX[2 * np][1],
                      bX[2 * np + 1][0], bX[2 * np + 1][1],
                      so + OFF_B + off);
            }
            #pragma unroll
            for (int mt = 0; mt < 2; ++mt)
                #pragma unroll
                for (int nt = 0; nt < 8; ++nt)
                    mma16816(acc[mt][nt], aW[mt], bX[nt]);
        }

        __syncthreads();       // all warps done with buffer (c+3)%4's previous use
        if (c + 3 < NCHUNK) issue(c + 3);
        CP_COMMIT();           // always commit to keep group counts aligned
    }

    // ---- Epilogue: registers -> gmem, + bias ----
    const int r0 = lane >> 2;
    const int cq = (lane & 3) * 2;
    #pragma unroll
    for (int mt = 0; mt < 2; ++mt) {
        const int row0 = oc0 + warp_m0 + mt * 16 + r0;
        const float bv0 = bias[row0];
        const float bv1 = bias[row0 + 8];
        float* p0 = out + ((size_t)(bb * NCH + row0)) * NL + l0 + warp_n0 + cq;
        float* p1 = p0 + (size_t)8 * NL;
        #pragma unroll
        for (int nt = 0; nt < 8; ++nt) {
            float2 v0 = { acc[mt][nt][0] + bv0, acc[mt][nt][1] + bv0 };
            float2 v1 = { acc[mt][nt][2] + bv1, acc[mt][nt][3] + bv1 };
            *(float2*)(p0 + nt * 8) = v0;
            *(float2*)(p1 + nt * 8) = v1;
        }
    }
}

// ============================================================================
// kernel_launch
//   d_in[0]=x   d_in[1]=W   d_in[2]=b (512)   d_in[3]=G   d_out f32
// ============================================================================
extern "C" void kernel_launch(void* const* d_in, const int* in_sizes, int n_in,
                              void* d_out, int out_size) {
    const float* x = (const float*)d_in[0];
    const float* W = (const float*)d_in[1];
    const float* b = (const float*)d_in[2];
    const float* G = (const float*)d_in[3];
    float* out = (float*)d_out;

    build_kern<<<(NTAP * NCH * NCH) / 256, 256>>>(W, G);
    build_x<<<dim3((NLP + 63) / 64, NCH / 32, NB), 256>>>(x);

    cudaFuncSetAttribute(gpconv_main,
                         cudaFuncAttributeMaxDynamicSharedMemorySize, DYN_SMEM);
    gpconv_main<<<dim3(NL / TN, NCH / TM, NB), 256, DYN_SMEM>>>(b, out);
}

// round 14
// speedup vs baseline: 2.2097x; 1.0870x over previous
#include <cuda_runtime.h>
#include <cuda_fp16.h>
#include <cstdint>

// ============================================================================
// GPConv1d: geometric-product conv == dense 1D conv after contracting G into W.
//   x: (8, 64, 8, 4096) f32   W: (5, 64, 64, 8) f32   b: (512) f32   G: (8,8,8) f32
//   out: (8, 64, 8, 4096) f32
//   GEMM-conv: Cout=Cin=512, taps=5, pad=2, L=4096, B=8
//
// Engine: single-pass fp16 mma.sync (HMMA, fp32 acc).  tcgen05 unusable:
// harness PTX target is sm_103 (non-'a') which rejects all tcgen05/TMEM ops.
//
// R12: fix R11's X-ring race (prefetch overwrote the in-read buffer) by
// deepening the X ring to 3 slots (ch % 3).  W ring depth 4 unchanged.
// ============================================================================
#define NB   8
#define NCH  512
#define NL   4096
#define NLP  4100
#define NTAP 5

#define TM   128            // oc per CTA
#define TN   256            // l per CTA
#define NITER 40            // 8 ic-chunks * 5 taps

#define WBUF  16384         // one W tile: 128 x 64 fp16, SW128 rows
#define XROWS 260           // TN + 4 halo rows
#define XBUF  33792         // 260*128 rounded up to 1KB
#define NXS   3             // X ring depth (fixes R11 race)
#define OFF_X (4*WBUF)      // 65536
#define DYN_SMEM (OFF_X + NXS*XBUF + 1024)   // 167936 B

// ============================================================================
// Device scratch (static __device__ arrays — sanctioned no-alloc scratch)
// ============================================================================
__device__ __align__(16) __half g_Wf[(size_t)NTAP * NCH * NCH];
__device__ __align__(16) __half g_Xf[(size_t)NB * NLP * NCH];

// ============================================================================
// Helpers (sm_80-baseline PTX; compiles for plain sm_103 target)
// ============================================================================
__device__ __forceinline__ uint32_t smem_u32(const void* p) {
    return (uint32_t)__cvta_generic_to_shared(p);
}

// SW128 swizzle within a 128B-row tile: 16B chunk c of row r -> chunk c^(r&7)
__device__ __forceinline__ uint32_t swz(uint32_t row, uint32_t colb) {
    return row * 128u + (colb ^ ((row & 7u) * 16u));
}

__device__ __forceinline__ void cp16(uint32_t dst, const void* src) {
    asm volatile("cp.async.cg.shared.global [%0], [%1], 16;"
                 :: "r"(dst), "l"(src));
}
#define CP_COMMIT() asm volatile("cp.async.commit_group;" ::: "memory")
#define CP_WAIT2()  asm volatile("cp.async.wait_group 2;" ::: "memory")

__device__ __forceinline__ void ldsm4(uint32_t& r0, uint32_t& r1,
                                      uint32_t& r2, uint32_t& r3, uint32_t a) {
    asm volatile("ldmatrix.sync.aligned.m8n8.x4.shared.b16 {%0,%1,%2,%3}, [%4];"
                 : "=r"(r0), "=r"(r1), "=r"(r2), "=r"(r3) : "r"(a));
}

__device__ __forceinline__ void mma16816(float* d, const uint32_t* a,
                                         const uint32_t* b) {
    asm volatile(
        "mma.sync.aligned.m16n8k16.row.col.f32.f16.f16.f32 "
        "{%0,%1,%2,%3}, {%4,%5,%6,%7}, {%8,%9}, {%0,%1,%2,%3};"
        : "+f"(d[0]), "+f"(d[1]), "+f"(d[2]), "+f"(d[3])
        : "r"(a[0]), "r"(a[1]), "r"(a[2]), "r"(a[3]), "r"(b[0]), "r"(b[1]));
}

// ============================================================================
// Precompute 1: kern_v[oc, ic] = G[j^k, j, k] * W[v, c, o, j^k]  -> fp16
//   oc = o*8 + k, ic = c*8 + j.   Layout: g_Wf[v][oc][ic]
// ============================================================================
__global__ void build_kern(const float* __restrict__ W, const float* __restrict__ G) {
    int idx = blockIdx.x * 256 + threadIdx.x;
    if (idx >= NTAP * NCH * NCH) return;
    int ic = idx & 511;
    int oc = (idx >> 9) & 511;
    int v  = idx >> 18;
    int o = oc >> 3, kb = oc & 7;
    int c = ic >> 3, j  = ic & 7;
    int i = j ^ kb;
    float sign = G[(i * 8 + j) * 8 + kb];
    float val  = sign * W[(((v * 64) + c) * 64 + o) * 8 + i];
    g_Wf[idx] = __float2half_rn(val);
}

// ============================================================================
// Precompute 2: padded transpose of x -> g_Xf[b][lp][ic]  fp16 (half2 stores)
//   x layout: [b][c][j][l], ic = c*8 + j, lp = l + 2 (pad 2 each side)
// ============================================================================
__global__ void build_x(const float* __restrict__ x) {
    __shared__ float s[64][65];
    const int tid = threadIdx.x;
    const int b   = blockIdx.z;
    const int ic0 = blockIdx.y * 64;
    const int lp0 = blockIdx.x * 64;

    for (int e = tid; e < 4096; e += 256) {
        int icl = e >> 6, lpl = e & 63;
        int lp = lp0 + lpl;
        int l  = lp - 2;
        int ic = ic0 + icl;
        int c = ic >> 3, j = ic & 7;
        float v = 0.f;
        if (l >= 0 && l < NL && lp < NLP)
            v = x[(((size_t)(b * 64 + c)) * 8 + j) * NL + l];
        s[icl][lpl] = v;
    }
    __syncthreads();
    for (int e = tid; e < 2048; e += 256) {
        int lpl = e >> 5, icl = (e & 31) * 2;
        int lp = lp0 + lpl;
        if (lp < NLP) {
            __half2 h = __floats2half2_rn(s[icl][lpl], s[icl + 1][lpl]);
            *(__half2*)(g_Xf + ((size_t)b * NLP + lp) * NCH + ic0 + icl) = h;
        }
    }
}

// ============================================================================
// Main kernel: tap-reuse pipelined fp16 HMMA GEMM conv.
//   Per CTA: D[128 oc, 256 l] fp32 in registers.
//   Loop: 8 ic-chunks x 5 taps.  X tile (260 rows) resident per ic-chunk;
//   B-operand rows slide by tap v.  W ring depth 4, X ring depth 3.
//   grid = (16 l-tiles, 4 oc-tiles, 8 batch), 256 threads (2x4 warps).
// ============================================================================
__global__ __launch_bounds__(256, 1)
void gpconv_main(const float* __restrict__ bias, float* __restrict__ out) {
    extern __shared__ char dsm_raw[];
    const int tid  = threadIdx.x;
    const int wid  = tid >> 5;
    const int lane = tid & 31;
    const int l0   = blockIdx.x * TN;
    const int oc0  = blockIdx.y * TM;
    const int bb   = blockIdx.z;

    const uint32_t raw   = smem_u32(dsm_raw);
    const uint32_t sbase = (raw + 1023u) & ~1023u;

    const int warp_m0 = (wid & 1) * 64;   // 2 warps over M=128 (4 m16 tiles)
    const int warp_n0 = (wid >> 1) * 64;  // 4 warps over N=256 (8 n8 tiles)

    float acc[4][8][4];
    #pragma unroll
    for (int mt = 0; mt < 4; ++mt)
        #pragma unroll
        for (int nt = 0; nt < 8; ++nt)
            #pragma unroll
            for (int q = 0; q < 4; ++q) acc[mt][nt][q] = 0.f;

    // ---- W tile loader: iteration t (tap = t%5, ic-chunk = t/5) -> ring t&3
    auto issueW = [&](int t) {
        const int v  = t % NTAP;
        const int ch = t / NTAP;
        const uint32_t so = sbase + (uint32_t)(t & 3) * WBUF;
        const size_t gb = (((size_t)v * NCH) + oc0) * NCH + (size_t)ch * 64;
        #pragma unroll
        for (int e = tid; e < 1024; e += 256) {
            int row = e >> 3, seg = e & 7;
            cp16(so + swz((uint32_t)row, (uint32_t)seg * 16u),
                 g_Wf + gb + (size_t)row * NCH + seg * 8);
        }
    };
    // ---- X tile loader: ic-chunk ch -> ring ch%3 (260 rows incl. 4-row halo)
    //      Slot (ch+2)%3 is distinct from the in-read slot ch%3 and the next
    //      slot (ch+1)%3, and its previous reader (chunk ch-1) retired before
    //      the barrier preceding this issue -> no write-while-read race.
    auto issueX = [&](int ch) {
        const uint32_t so = sbase + OFF_X + (uint32_t)(ch % NXS) * XBUF;
        const size_t xb = (((size_t)bb * NLP) + (size_t)l0) * NCH + (size_t)ch * 64;
        for (int e = tid; e < XROWS * 8; e += 256) {
            int row = e >> 3, seg = e & 7;
            cp16(so + swz((uint32_t)row, (uint32_t)seg * 16u),
                 g_Xf + xb + (size_t)row * NCH + seg * 8);
        }
    };

    // Prologue groups: C0={X0,X1,W0}, C1={W1}, C2={W2}
    issueX(0); issueX(1); issueW(0); CP_COMMIT();
    issueW(1); CP_COMMIT();
    issueW(2); CP_COMMIT();

    // per-lane ldmatrix address components
    const uint32_t a_row = lane & 15;
    const uint32_t a_col = (uint32_t)(lane >> 4) * 16u;
    const uint32_t b_row = (uint32_t)((lane & 7) | ((lane & 16) >> 1));
    const uint32_t b_col = (uint32_t)((lane >> 3) & 1) * 16u;

    int v = 0, ch = 0;
    for (int t = 0; t < NITER; ++t) {
        CP_WAIT2();                 // groups 0..t complete (2 still pending)
        __syncthreads();            // data visible to all; prior reads retired

        // Issue group t+3: W[t+3] (+ X[ch+2] at the start of each ic-chunk)
        if (t + 3 < NITER) issueW(t + 3);
        if (v == 0 && ch + 2 < 8) issueX(ch + 2);
        CP_COMMIT();

        const uint32_t soW = sbase + (uint32_t)(t & 3) * WBUF;
        const uint32_t soX = sbase + OFF_X + (uint32_t)(ch % NXS) * XBUF;
        const uint32_t b_row_v = b_row + (uint32_t)v;   // tap slide

        #pragma unroll
        for (int s = 0; s < 4; ++s) {
            uint32_t aW[4][4], bX[8][2];
            #pragma unroll
            for (int mt = 0; mt < 4; ++mt)
                ldsm4(aW[mt][0], aW[mt][1], aW[mt][2], aW[mt][3],
                      soW + swz((uint32_t)(warp_m0 + mt * 16) + a_row,
                                (uint32_t)s * 32u + a_col));
            #pragma unroll
            for (int np = 0; np < 4; ++np)
                ldsm4(bX[2 * np][0], bX[2 * np][1],
                      bX[2 * np + 1][0], bX[2 * np + 1][1],
                      soX + swz((uint32_t)(warp_n0 + np * 16) + b_row_v,
                                (uint32_t)s * 32u + b_col));
            #pragma unroll
            for (int mt = 0; mt < 4; ++mt)
                #pragma unroll
                for (int nt = 0; nt < 8; ++nt)
                    mma16816(acc[mt][nt], aW[mt], bX[nt]);
        }

        if (++v == NTAP) { v = 0; ++ch; }
    }

    // ---- Epilogue: registers -> gmem, + bias ----
    const int r0 = lane >> 2;
    const int cq = (lane & 3) * 2;
    #pragma unroll
    for (int mt = 0; mt < 4; ++mt) {
        const int row0 = oc0 + warp_m0 + mt * 16 + r0;
        const float bv0 = bias[row0];
        const float bv1 = bias[row0 + 8];
        float* p0 = out + ((size_t)(bb * NCH + row0)) * NL + l0 + warp_n0 + cq;
        float* p1 = p0 + (size_t)8 * NL;
        #pragma unroll
        for (int nt = 0; nt < 8; ++nt) {
            float2 v0 = { acc[mt][nt][0] + bv0, acc[mt][nt][1] + bv0 };
            float2 v1 = { acc[mt][nt][2] + bv1, acc[mt][nt][3] + bv1 };
            *(float2*)(p0 + nt * 8) = v0;
            *(float2*)(p1 + nt * 8) = v1;
        }
    }
}

// ============================================================================
// kernel_launch
//   d_in[0]=x   d_in[1]=W   d_in[2]=b (512)   d_in[3]=G   d_out f32
// ============================================================================
extern "C" void kernel_launch(void* const* d_in, const int* in_sizes, int n_in,
                              void* d_out, int out_size) {
    const float* x = (const float*)d_in[0];
    const float* W = (const float*)d_in[1];
    const float* b = (const float*)d_in[2];
    const float* G = (const float*)d_in[3];
    float* out = (float*)d_out;

    build_kern<<<(NTAP * NCH * NCH) / 256, 256>>>(W, G);
    build_x<<<dim3((NLP + 63) / 64, NCH / 64, NB), 256>>>(x);

    cudaFuncSetAttribute(gpconv_main,
                         cudaFuncAttributeMaxDynamicSharedMemorySize, DYN_SMEM);
    gpconv_main<<<dim3(NL / TN, NCH / TM, NB), 256, DYN_SMEM>>>(b, out);
}

// round 16
// speedup vs baseline: 2.5607x; 1.1588x over previous
#include <cuda_runtime.h>
#include <cuda_fp16.h>
#include <cstdint>

// ============================================================================
// GPConv1d: geometric-product conv == dense 1D conv after contracting G into W.
//   x: (8, 64, 8, 4096) f32   W: (5, 64, 64, 8) f32   b: (512) f32   G: (8,8,8) f32
//   out: (8, 64, 8, 4096) f32
//   GEMM-conv: Cout=Cin=512, taps=5, pad=2, L=4096, B=8
//
// Engine: single-pass fp16 mma.sync (HMMA, fp32 acc).  tcgen05 unusable:
// harness PTX target is sm_103 (non-'a') which rejects all tcgen05/TMEM ops.
//
// R14 -> R15: occupancy experiment.  TN=128, W ring 3 (dist 2) + X ring 2
// (dist 1) = 83 KB smem -> 2 CTAs/SM (4 warps/SMSP) to cover LDSM->MMA
// latency and barrier gaps.  Tap-reuse of X kept.
// ============================================================================
#define NB   8
#define NCH  512
#define NL   4096
#define NLP  4100
#define NTAP 5

#define TM   128            // oc per CTA
#define TN   128            // l per CTA
#define NITER 40            // 8 ic-chunks * 5 taps

#define WBUF  16384         // one W tile: 128 x 64 fp16, SW128 rows
#define NWS   3             // W ring depth (prefetch distance 2)
#define XROWS 132           // TN + 4 halo rows
#define XBUF  16896         // 132*128 bytes
#define NXS   2             // X ring depth (prefetch distance 1)
#define OFF_X (NWS*WBUF)    // 49152
#define DYN_SMEM (OFF_X + NXS*XBUF)   // 82944 B -> 2 CTAs/SM

// ============================================================================
// Device scratch (static __device__ arrays — sanctioned no-alloc scratch)
// ============================================================================
__device__ __align__(16) __half g_Wf[(size_t)NTAP * NCH * NCH];
__device__ __align__(16) __half g_Xf[(size_t)NB * NLP * NCH];

// ============================================================================
// Helpers (sm_80-baseline PTX; compiles for plain sm_103 target)
// ============================================================================
__device__ __forceinline__ uint32_t smem_u32(const void* p) {
    return (uint32_t)__cvta_generic_to_shared(p);
}

// SW128 swizzle within a 128B-row tile: 16B chunk c of row r -> chunk c^(r&7)
__device__ __forceinline__ uint32_t swz(uint32_t row, uint32_t colb) {
    return row * 128u + (colb ^ ((row & 7u) * 16u));
}

__device__ __forceinline__ void cp16(uint32_t dst, const void* src) {
    asm volatile("cp.async.cg.shared.global [%0], [%1], 16;"
                 :: "r"(dst), "l"(src));
}
#define CP_COMMIT() asm volatile("cp.async.commit_group;" ::: "memory")
#define CP_WAIT1()  asm volatile("cp.async.wait_group 1;" ::: "memory")

__device__ __forceinline__ void ldsm4(uint32_t& r0, uint32_t& r1,
                                      uint32_t& r2, uint32_t& r3, uint32_t a) {
    asm volatile("ldmatrix.sync.aligned.m8n8.x4.shared.b16 {%0,%1,%2,%3}, [%4];"
                 : "=r"(r0), "=r"(r1), "=r"(r2), "=r"(r3) : "r"(a));
}

__device__ __forceinline__ void mma16816(float* d, const uint32_t* a,
                                         const uint32_t* b) {
    asm volatile(
        "mma.sync.aligned.m16n8k16.row.col.f32.f16.f16.f32 "
        "{%0,%1,%2,%3}, {%4,%5,%6,%7}, {%8,%9}, {%0,%1,%2,%3};"
        : "+f"(d[0]), "+f"(d[1]), "+f"(d[2]), "+f"(d[3])
        : "r"(a[0]), "r"(a[1]), "r"(a[2]), "r"(a[3]), "r"(b[0]), "r"(b[1]));
}

// ============================================================================
// Precompute 1: kern_v[oc, ic] = G[j^k, j, k] * W[v, c, o, j^k]  -> fp16
//   oc = o*8 + k, ic = c*8 + j.   Layout: g_Wf[v][oc][ic].  4 elems/thread.
// ============================================================================
__global__ void build_kern(const float* __restrict__ W, const float* __restrict__ G) {
    int base = (blockIdx.x * 256 + threadIdx.x) * 4;
    if (base >= NTAP * NCH * NCH) return;
    ushort4 pack;
    unsigned short* ps = (unsigned short*)&pack;
    #pragma unroll
    for (int q = 0; q < 4; ++q) {
        int idx = base + q;
        int ic = idx & 511;
        int oc = (idx >> 9) & 511;
        int v  = idx >> 18;
        int o = oc >> 3, kb = oc & 7;
        int c = ic >> 3, j  = ic & 7;
        int i = j ^ kb;
        float sign = G[(i * 8 + j) * 8 + kb];
        float val  = sign * W[(((v * 64) + c) * 64 + o) * 8 + i];
        __half h = __float2half_rn(val);
        ps[q] = *(unsigned short*)&h;
    }
    *(ushort4*)(g_Wf + base) = pack;
}

// ============================================================================
// Precompute 2: padded transpose of x -> g_Xf[b][lp][ic]  fp16 (half2 stores)
//   x layout: [b][c][j][l], ic = c*8 + j, lp = l + 2 (pad 2 each side)
// ============================================================================
__global__ void build_x(const float* __restrict__ x) {
    __shared__ float s[64][65];
    const int tid = threadIdx.x;
    const int b   = blockIdx.z;
    const int ic0 = blockIdx.y * 64;
    const int lp0 = blockIdx.x * 64;

    for (int e = tid; e < 4096; e += 256) {
        int icl = e >> 6, lpl = e & 63;
        int lp = lp0 + lpl;
        int l  = lp - 2;
        int ic = ic0 + icl;
        int c = ic >> 3, j = ic & 7;
        float v = 0.f;
        if (l >= 0 && l < NL && lp < NLP)
            v = x[(((size_t)(b * 64 + c)) * 8 + j) * NL + l];
        s[icl][lpl] = v;
    }
    __syncthreads();
    for (int e = tid; e < 2048; e += 256) {
        int lpl = e >> 5, icl = (e & 31) * 2;
        int lp = lp0 + lpl;
        if (lp < NLP) {
            __half2 h = __floats2half2_rn(s[icl][lpl], s[icl + 1][lpl]);
            *(__half2*)(g_Xf + ((size_t)b * NLP + lp) * NCH + ic0 + icl) = h;
        }
    }
}

// ============================================================================
// Main kernel: tap-reuse pipelined fp16 HMMA GEMM conv, 2 CTAs/SM.
//   Per CTA: D[128 oc, 128 l] fp32 in registers.
//   Loop: 8 ic-chunks x 5 taps.  X tile (132 rows) resident per ic-chunk;
//   B-operand rows slide by tap v.  W ring 3 (dist 2), X ring 2 (dist 1).
//   Group ledger: prologue commits G0={X0,W0}, G1={X1,W1}; iter t commits
//   G_{t+2}={W[t+2] (+X[ch+1] at v==0)}.  wait_group 1 at top of iter t
//   guarantees G0..G_t complete.
//   grid = (32 l-tiles, 4 oc-tiles, 8 batch), 256 threads (2x4 warps).
// ============================================================================
__global__ __launch_bounds__(256, 2)
void gpconv_main(const float* __restrict__ bias, float* __restrict__ out) {
    extern __shared__ char dsm_raw[];
    const int tid  = threadIdx.x;
    const int wid  = tid >> 5;
    const int lane = tid & 31;
    const int l0   = blockIdx.x * TN;
    const int oc0  = blockIdx.y * TM;
    const int bb   = blockIdx.z;

    const uint32_t sbase = smem_u32(dsm_raw);   // 1024-aligned by attr (82944%1024==0)

    const int warp_m0 = (wid & 1) * 64;   // 2 warps over M=128 (4 m16 tiles)
    const int warp_n0 = (wid >> 1) * 32;  // 4 warps over N=128 (4 n8 tiles)

    float acc[4][4][4];
    #pragma unroll
    for (int mt = 0; mt < 4; ++mt)
        #pragma unroll
        for (int nt = 0; nt < 4; ++nt)
            #pragma unroll
            for (int q = 0; q < 4; ++q) acc[mt][nt][q] = 0.f;

    // ---- W tile loader: iteration t (tap = t%5, ic-chunk = t/5) -> ring t%3
    auto issueW = [&](int t) {
        const int v  = t % NTAP;
        const int ch = t / NTAP;
        const uint32_t so = sbase + (uint32_t)(t % NWS) * WBUF;
        const size_t gb = (((size_t)v * NCH) + oc0) * NCH + (size_t)ch * 64;
        #pragma unroll
        for (int e = tid; e < 1024; e += 256) {
            int row = e >> 3, seg = e & 7;
            cp16(so + swz((uint32_t)row, (uint32_t)seg * 16u),
                 g_Wf + gb + (size_t)row * NCH + seg * 8);
        }
    };
    // ---- X tile loader: ic-chunk ch -> ring ch&1 (132 rows incl. 4-row halo)
    //      Write slot (ch+1)&1 while reading ch&1; previous reader (chunk
    //      ch-1) retired before the barrier preceding the issue -> no race.
    auto issueX = [&](int ch) {
        const uint32_t so = sbase + OFF_X + (uint32_t)(ch & 1) * XBUF;
        const size_t xb = (((size_t)bb * NLP) + (size_t)l0) * NCH + (size_t)ch * 64;
        for (int e = tid; e < XROWS * 8; e += 256) {
            int row = e >> 3, seg = e & 7;
            cp16(so + swz((uint32_t)row, (uint32_t)seg * 16u),
                 g_Xf + xb + (size_t)row * NCH + seg * 8);
        }
    };

    // Prologue: G0={X0,W0}, G1={X1,W1}
    issueX(0); issueW(0); CP_COMMIT();
    issueX(1); issueW(1); CP_COMMIT();

    // per-lane ldmatrix address components
    const uint32_t a_row = lane & 15;
    const uint32_t a_col = (uint32_t)(lane >> 4) * 16u;
    const uint32_t b_row = (uint32_t)((lane & 7) | ((lane & 16) >> 1));
    const uint32_t b_col = (uint32_t)((lane >> 3) & 1) * 16u;

    int v = 0, ch = 0;
    for (int t = 0; t < NITER; ++t) {
        CP_WAIT1();                 // groups G0..G_t complete (<=1 pending)
        __syncthreads();            // data visible; prior-iter reads retired

        // Issue group G_{t+2}: W[t+2] (+ X[ch+1] at the start of each chunk)
        if (t + 2 < NITER) issueW(t + 2);
        if (v == 0 && ch + 1 < 8) issueX(ch + 1);
        CP_COMMIT();

        const uint32_t soW = sbase + (uint32_t)(t % NWS) * WBUF;
        const uint32_t soX = sbase + OFF_X + (uint32_t)(ch & 1) * XBUF;
        const uint32_t b_row_v = b_row + (uint32_t)v;   // tap slide

        #pragma unroll
        for (int s = 0; s < 4; ++s) {
            uint32_t aW[4][4], bX[4][2];
            #pragma unroll
            for (int mt = 0; mt < 4; ++mt)
                ldsm4(aW[mt][0], aW[mt][1], aW[mt][2], aW[mt][3],
                      soW + swz((uint32_t)(warp_m0 + mt * 16) + a_row,
                                (uint32_t)s * 32u + a_col));
            #pragma unroll
            for (int np = 0; np < 2; ++np)
                ldsm4(bX[2 * np][0], bX[2 * np][1],
                      bX[2 * np + 1][0], bX[2 * np + 1][1],
                      soX + swz((uint32_t)(warp_n0 + np * 16) + b_row_v,
                                (uint32_t)s * 32u + b_col));
            #pragma unroll
            for (int mt = 0; mt < 4; ++mt)
                #pragma unroll
                for (int nt = 0; nt < 4; ++nt)
                    mma16816(acc[mt][nt], aW[mt], bX[nt]);
        }

        if (++v == NTAP) { v = 0; ++ch; }
    }

    // ---- Epilogue: registers -> gmem, + bias ----
    const int r0 = lane >> 2;
    const int cq = (lane & 3) * 2;
    #pragma unroll
    for (int mt = 0; mt < 4; ++mt) {
        const int row0 = oc0 + warp_m0 + mt * 16 + r0;
        const float bv0 = bias[row0];
        const float bv1 = bias[row0 + 8];
        float* p0 = out + ((size_t)(bb * NCH + row0)) * NL + l0 + warp_n0 + cq;
        float* p1 = p0 + (size_t)8 * NL;
        #pragma unroll
        for (int nt = 0; nt < 4; ++nt) {
            float2 v0 = { acc[mt][nt][0] + bv0, acc[mt][nt][1] + bv0 };
            float2 v1 = { acc[mt][nt][2] + bv1, acc[mt][nt][3] + bv1 };
            *(float2*)(p0 + nt * 8) = v0;
            *(float2*)(p1 + nt * 8) = v1;
        }
    }
}

// ============================================================================
// kernel_launch
//   d_in[0]=x   d_in[1]=W   d_in[2]=b (512)   d_in[3]=G   d_out f32
// ============================================================================
extern "C" void kernel_launch(void* const* d_in, const int* in_sizes, int n_in,
                              void* d_out, int out_size) {
    const float* x = (const float*)d_in[0];
    const float* W = (const float*)d_in[1];
    const float* b = (const float*)d_in[2];
    const float* G = (const float*)d_in[3];
    float* out = (float*)d_out;

    build_kern<<<(NTAP * NCH * NCH) / 1024, 256>>>(W, G);
    build_x<<<dim3((NLP + 63) / 64, NCH / 64, NB), 256>>>(x);

    cudaFuncSetAttribute(gpconv_main,
                         cudaFuncAttributeMaxDynamicSharedMemorySize, DYN_SMEM);
    gpconv_main<<<dim3(NL / TN, NCH / TM, NB), 256, DYN_SMEM>>>(b, out);
}